// round 1
// baseline (speedup 1.0000x reference)
#include <cuda_runtime.h>
#include <math.h>

// ---------------- constants ----------------
#define NB 16
#define HIN 512
#define C1 64
#define H1 256          // stem conv out 256x256
#define HP 128          // after 3x3 s2 p1 pool
#define CH 704
#define NP 23           // roialign pool
#define CONV1_OUT 21
#define PI_D 3.14159265358979323846

// ---------------- device scratch ----------------
__device__ float g_conv0[(size_t)NB*C1*H1*H1];       // 256 MB
__device__ float g_f   [(size_t)NB*C1*HP*HP];        // 64 MB
__device__ float g_xt1 [(size_t)NB*C1*HP*HP];
__device__ float g_xt2 [(size_t)NB*C1*HP*HP];
__device__ float g_h   [(size_t)NB*CH*NP*NP];
__device__ float g_c1p [(size_t)8*NB*64*441];
__device__ float g_c1  [(size_t)NB*64*441];
__device__ float g_p1  [(size_t)NB*64*100];
__device__ float g_c2  [(size_t)NB*32*64];
__device__ float g_fc1 [(size_t)NB*128];
__device__ float2 g_bn0part[64*8];
__device__ float g_scale0[64], g_shift0[64];
__device__ float g_scale1[64], g_shift1[64];

// ---------------- stem conv: 7x7 s2 p3, 3->64 ch ----------------
// thread = 1 output pixel, 64 output channels in registers; weights in smem.
__global__ __launch_bounds__(128) void stem_kernel(const float* __restrict__ x,
                                                   const float* __restrict__ w) {
    __shared__ float ws[147*64];   // [idx][co], idx = c*49+kh*7+kw
    int b = blockIdx.y;
    int p = blockIdx.x*128 + threadIdx.x;
    for (int i = threadIdx.x; i < 9408; i += 128) {
        int co = i / 147, idx = i % 147;
        ws[idx*64 + co] = w[i];
    }
    __syncthreads();
    int oh = p >> 8, ow = p & 255;
    float acc[64];
#pragma unroll
    for (int i = 0; i < 64; i++) acc[i] = 0.f;
    const float4* ws4 = (const float4*)ws;
    for (int c = 0; c < 3; c++) {
        for (int kh = 0; kh < 7; kh++) {
            int ih = oh*2 - 3 + kh;
            bool vrow = ((unsigned)ih < 512u);
            const float* xrow = x + (((size_t)b*512 + ih)*512)*3 + c;
#pragma unroll
            for (int kw = 0; kw < 7; kw++) {
                int iw = ow*2 - 3 + kw;
                float v = (vrow && (unsigned)iw < 512u) ? xrow[iw*3] : 0.f;
                int idx = (c*7 + kh)*7 + kw;
                const float4* wp = ws4 + idx*16;
#pragma unroll
                for (int g = 0; g < 16; g++) {
                    float4 wv = wp[g];
                    acc[g*4+0] += v*wv.x;
                    acc[g*4+1] += v*wv.y;
                    acc[g*4+2] += v*wv.z;
                    acc[g*4+3] += v*wv.w;
                }
            }
        }
    }
    size_t base = ((size_t)b*64)*65536 + p;
#pragma unroll
    for (int co = 0; co < 64; co++) g_conv0[base + (size_t)co*65536] = acc[co];
}

// ---------------- bn0 stats (deterministic two-stage) ----------------
__global__ void bn0_partial() {
    int c = blockIdx.x, sl = blockIdx.y;
    float s = 0.f, q = 0.f;
    for (int j = sl*131072 + threadIdx.x; j < (sl+1)*131072; j += 256) {
        int b = j >> 16, pix = j & 65535;
        float v = g_conv0[((size_t)(b*64 + c))*65536 + pix];
        s += v; q += v*v;
    }
    __shared__ float rs[256], rq[256];
    rs[threadIdx.x] = s; rq[threadIdx.x] = q; __syncthreads();
    for (int st = 128; st > 0; st >>= 1) {
        if (threadIdx.x < st) { rs[threadIdx.x] += rs[threadIdx.x+st]; rq[threadIdx.x] += rq[threadIdx.x+st]; }
        __syncthreads();
    }
    if (threadIdx.x == 0) g_bn0part[c*8 + sl] = make_float2(rs[0], rq[0]);
}

__global__ void bn0_final(const float* __restrict__ g, const float* __restrict__ bb) {
    int c = threadIdx.x; if (c >= 64) return;
    float s = 0.f, q = 0.f;
    for (int i = 0; i < 8; i++) { float2 p = g_bn0part[c*8+i]; s += p.x; q += p.y; }
    const float inv = 1.f / 1048576.f;
    float m = s*inv, var = q*inv - m*m;
    float sc = g[c] * rsqrtf(var + 1e-5f);
    g_scale0[c] = sc; g_shift0[c] = bb[c] - m*sc;
}

// ---------------- fused bn+relu+maxpool 3x3 s2 p1 ----------------
__global__ void pool0() {
    int idx = blockIdx.x*256 + threadIdx.x;          // 16*64*128*128 total
    int ow = idx & 127, oh = (idx >> 7) & 127, c = (idx >> 14) & 63, b = idx >> 20;
    float sc = g_scale0[c], sh = g_shift0[c];
    const float* src = g_conv0 + ((size_t)(b*64 + c))*65536;
    float m = 0.f;   // relu >= 0, window non-empty
#pragma unroll
    for (int dy = 0; dy < 3; dy++) {
        int ih = oh*2 - 1 + dy;
        if ((unsigned)ih >= 256u) continue;
#pragma unroll
        for (int dx = 0; dx < 3; dx++) {
            int iw = ow*2 - 1 + dx;
            if ((unsigned)iw >= 256u) continue;
            m = fmaxf(m, fmaxf(sc*src[ih*256 + iw] + sh, 0.f));
        }
    }
    g_f[idx] = m;
}

// ---------------- grid_sample with affine grid ----------------
__global__ void gridsample_kernel(float t00, float t01, float t02,
                                  float t10, float t11, float t12, int which) {
    int w = threadIdx.x, hh = blockIdx.x, b = blockIdx.y;
    float* out = which ? g_xt2 : g_xt1;
    float gx = (float)(2*w + 1) * (1.f/128.f) - 1.f;
    float gy = (float)(2*hh + 1) * (1.f/128.f) - 1.f;
    float grx = gx*t00 + gy*t01 + t02;
    float gry = gx*t10 + gy*t11 + t12;
    float ix = ((grx + 1.f)*128.f - 1.f)*0.5f;
    float iy = ((gry + 1.f)*128.f - 1.f)*0.5f;
    float x0f = floorf(ix), y0f = floorf(iy);
    int x0 = (int)x0f, y0 = (int)y0f;
    float wa = (x0f + 1.f - ix)*(y0f + 1.f - iy);
    float wb = (x0f + 1.f - ix)*(iy - y0f);
    float wc = (ix - x0f)*(y0f + 1.f - iy);
    float wd = (ix - x0f)*(iy - y0f);
    int   off[4]; float wf[4];
    float wt[4] = {wa, wb, wc, wd};   // (dx,dy): (0,0),(0,1),(1,0),(1,1)
    int xs2[2] = {x0, x0 + 1}, ys2[2] = {y0, y0 + 1};
#pragma unroll
    for (int dx = 0; dx < 2; dx++)
#pragma unroll
        for (int dy = 0; dy < 2; dy++) {
            int xx = xs2[dx], yy = ys2[dy];
            bool valid = ((unsigned)xx < 128u) && ((unsigned)yy < 128u);
            int xc = min(max(xx, 0), 127), yc = min(max(yy, 0), 127);
            int k = dx*2 + dy;
            off[k] = yc*128 + xc;
            wf[k] = valid ? wt[k] : 0.f;
        }
    size_t base = ((size_t)b*64)*16384;
    int pix = hh*128 + w;
    const float* src = g_f + base;
    for (int c = 0; c < 64; c++) {
        const float* sp = src + c*16384;
        out[base + (size_t)c*16384 + pix] =
            sp[off[0]]*wf[0] + sp[off[1]]*wf[1] + sp[off[2]]*wf[2] + sp[off[3]]*wf[3];
    }
}

// ---------------- roialign: writes directly into concat buffer g_h ----------------
__global__ void roialign_kernel(const float* __restrict__ box) {
    int blk = blockIdx.x;            // 16*11
    int b = blk / 11, s = blk % 11;
    const float* feat; int r;
    if (s < 7)       { feat = g_f;   r = s;     }
    else if (s < 9)  { feat = g_xt1; r = s - 7; }
    else             { feat = g_xt2; r = s - 9; }
    const float* bx = box + b*28 + r*4;
    float rx1 = bx[0]*0.25f, ry1 = bx[1]*0.25f, rx2 = bx[2]*0.25f, ry2 = bx[3]*0.25f;
    float bw = fmaxf(rx2 - rx1, 1.f) * (1.f/23.f);
    float bh = fmaxf(ry2 - ry1, 1.f) * (1.f/23.f);
    __shared__ int   sy0[46], sy1[46], sx0[46], sx1[46];
    __shared__ float sly[46], slx[46];
    __shared__ int   sey[46], sex[46];
    int t = threadIdx.x;
    if (t < 46) {
        float pos = (float)(t >> 1) + 0.25f + 0.5f*(float)(t & 1);
        float yv = ry1 + pos*bh;
        sey[t] = (yv < -1.f) || (yv > 128.f);
        float y = fminf(fmaxf(yv, 0.f), 127.f);
        float y0f = floorf(y); int y0 = (int)y0f;
        sy0[t] = y0; sy1[t] = min(y0 + 1, 127); sly[t] = y - y0f;
        float xv = rx1 + pos*bw;
        sex[t] = (xv < -1.f) || (xv > 128.f);
        float xx = fminf(fmaxf(xv, 0.f), 127.f);
        float x0f = floorf(xx); int x0 = (int)x0f;
        sx0[t] = x0; sx1[t] = min(x0 + 1, 127); slx[t] = xx - x0f;
    }
    __syncthreads();
    const float* fb = feat + ((size_t)b*64)*16384;
    float* ob = g_h + ((size_t)(b*704 + s*64))*529;
    for (int o = t; o < 64*529; o += 256) {
        int c = o / 529, pp = o % 529;
        int py = pp / 23, px = pp % 23;
        const float* img = fb + (size_t)c*16384;
        float acc = 0.f;
#pragma unroll
        for (int dy = 0; dy < 2; dy++) {
            int jy = py*2 + dy;
            int yy0 = sy0[jy], yy1 = sy1[jy];
            float ly = sly[jy], hy = 1.f - ly;
            int ey = sey[jy];
#pragma unroll
            for (int dx = 0; dx < 2; dx++) {
                int jx = px*2 + dx;
                int xx0 = sx0[jx], xx1 = sx1[jx];
                float lx = slx[jx], hx = 1.f - lx;
                float v = img[yy0*128 + xx0]*(hy*hx) + img[yy0*128 + xx1]*(hy*lx)
                        + img[yy1*128 + xx0]*(ly*hx) + img[yy1*128 + xx1]*(ly*lx);
                if (ey || sex[jx]) v = 0.f;
                acc += v;
            }
        }
        ob[o] = acc * 0.25f;
    }
}

// ---------------- conv1 3x3 valid, 704->64, ci-split partials ----------------
__global__ __launch_bounds__(448) void conv1_kernel(const float* __restrict__ w) {
    int split = blockIdx.x;   // 0..7 (88 ci each)
    int cog   = blockIdx.y;   // 0..3 (16 couts each)
    int b     = blockIdx.z;
    __shared__ float tile[529];
    __shared__ float ws[144];            // [k][co_local]
    int t = threadIdx.x;
    int oh = t / 21, ow = t % 21;
    bool active = (t < 441);
    float acc[16];
#pragma unroll
    for (int i = 0; i < 16; i++) acc[i] = 0.f;
    int ci0 = split*88;
    for (int ci = ci0; ci < ci0 + 88; ci++) {
        __syncthreads();
        for (int i = t; i < 529; i += 448)
            tile[i] = g_h[((size_t)(b*704 + ci))*529 + i];
        if (t < 144) {
            int j = t / 9, k = t % 9;
            ws[k*16 + j] = w[((size_t)(cog*16 + j)*704 + ci)*9 + k];
        }
        __syncthreads();
        if (active) {
            float r[9];
#pragma unroll
            for (int kh = 0; kh < 3; kh++)
#pragma unroll
                for (int kw = 0; kw < 3; kw++)
                    r[kh*3 + kw] = tile[(oh + kh)*23 + ow + kw];
            const float4* w4 = (const float4*)ws;
#pragma unroll
            for (int k = 0; k < 9; k++) {
                float rv = r[k];
#pragma unroll
                for (int g = 0; g < 4; g++) {
                    float4 wv = w4[k*4 + g];
                    acc[g*4+0] += rv*wv.x;
                    acc[g*4+1] += rv*wv.y;
                    acc[g*4+2] += rv*wv.z;
                    acc[g*4+3] += rv*wv.w;
                }
            }
        }
    }
    if (active) {
#pragma unroll
        for (int j = 0; j < 16; j++) {
            int co = cog*16 + j;
            g_c1p[(((size_t)split*16 + b)*64 + co)*441 + t] = acc[j];
        }
    }
}

__global__ void conv1_reduce() {
    int o = blockIdx.x*256 + threadIdx.x;
    if (o >= 16*64*441) return;
    float s = 0.f;
#pragma unroll
    for (int k = 0; k < 8; k++) s += g_c1p[(size_t)k*16*64*441 + o];
    g_c1[o] = s;
}

// ---------------- bn1 stats ----------------
__global__ void bn1_stats(const float* __restrict__ g, const float* __restrict__ bb) {
    int c = blockIdx.x;
    float s = 0.f, q = 0.f;
    for (int i = threadIdx.x; i < 16*441; i += 256) {
        int b = i / 441, t = i % 441;
        float v = g_c1[((size_t)(b*64 + c))*441 + t];
        s += v; q += v*v;
    }
    __shared__ float rs[256], rq[256];
    rs[threadIdx.x] = s; rq[threadIdx.x] = q; __syncthreads();
    for (int st = 128; st > 0; st >>= 1) {
        if (threadIdx.x < st) { rs[threadIdx.x] += rs[threadIdx.x+st]; rq[threadIdx.x] += rq[threadIdx.x+st]; }
        __syncthreads();
    }
    if (threadIdx.x == 0) {
        const float inv = 1.f / 7056.f;
        float m = rs[0]*inv, var = rq[0]*inv - m*m;
        float sc = g[c] * rsqrtf(var + 1e-5f);
        g_scale1[c] = sc; g_shift1[c] = bb[c] - m*sc;
    }
}

// ---------------- bn1+relu+maxpool2x2 ----------------
__global__ void pool1() {
    int idx = blockIdx.x*256 + threadIdx.x;   // 16*64*100
    if (idx >= 102400) return;
    int ow = idx % 10, oh = (idx/10) % 10, c = (idx/100) % 64, b = idx/6400;
    float sc = g_scale1[c], sh = g_shift1[c];
    const float* src = g_c1 + ((size_t)(b*64 + c))*441;
    float m = 0.f;
#pragma unroll
    for (int dy = 0; dy < 2; dy++)
#pragma unroll
        for (int dx = 0; dx < 2; dx++)
            m = fmaxf(m, fmaxf(sc*src[(oh*2 + dy)*21 + ow*2 + dx] + sh, 0.f));
    g_p1[idx] = m;
}

// ---------------- conv2 3x3 valid, 64->32, +bias, relu ----------------
__global__ void conv2_kernel(const float* __restrict__ w, const float* __restrict__ bias) {
    int idx = blockIdx.x*256 + threadIdx.x;   // 16*32*64
    int ow = idx & 7, oh = (idx >> 3) & 7, co = (idx >> 6) & 31, b = idx >> 11;
    const float* src = g_p1 + (size_t)b*6400;
    const float* wp  = w + (size_t)co*576;
    float acc = bias[co];
    for (int ci = 0; ci < 64; ci++) {
        const float* sp = src + ci*100;
        const float* wc = wp + ci*9;
#pragma unroll
        for (int kh = 0; kh < 3; kh++)
#pragma unroll
            for (int kw = 0; kw < 3; kw++)
                acc += sp[(oh + kh)*10 + ow + kw] * wc[kh*3 + kw];
    }
    g_c2[idx] = fmaxf(acc, 0.f);
}

// ---------------- fc1 + relu ----------------
__global__ __launch_bounds__(128) void fc1_kernel(const float* __restrict__ w, const float* __restrict__ bias) {
    int b = blockIdx.x, j = threadIdx.x;
    __shared__ float xv[2048];
    for (int i = j; i < 2048; i += 128) xv[i] = g_c2[(size_t)b*2048 + i];
    __syncthreads();
    const float4* wp = (const float4*)(w + (size_t)j*2048);
    const float4* xp = (const float4*)xv;
    float acc = 0.f;
#pragma unroll 4
    for (int k = 0; k < 512; k++) {
        float4 wv = wp[k], x4 = xp[k];
        acc += wv.x*x4.x + wv.y*x4.y + wv.z*x4.z + wv.w*x4.w;
    }
    g_fc1[b*128 + j] = fmaxf(acc + bias[j], 0.f);
}

// ---------------- head + tanh ----------------
__global__ void head_kernel(const float* __restrict__ w, const float* __restrict__ bias,
                            float* __restrict__ out) {
    int t = threadIdx.x; if (t >= 192) return;
    int b = t / 12, j = t % 12;
    const float* wp = w + j*128;
    const float* xp = g_fc1 + b*128;
    float acc = bias[j];
#pragma unroll 4
    for (int k = 0; k < 128; k++) acc += wp[k]*xp[k];
    out[b*12 + j] = tanhf(acc);
}

// ---------------- launch ----------------
extern "C" void kernel_launch(void* const* d_in, const int* in_sizes, int n_in,
                              void* d_out, int out_size) {
    const float* x       = (const float*)d_in[0];
    const float* box     = (const float*)d_in[1];
    const float* stem_w  = (const float*)d_in[2];
    const float* stem_g  = (const float*)d_in[3];
    const float* stem_b  = (const float*)d_in[4];
    const float* conv1_w = (const float*)d_in[5];
    /* conv1_b (d_in[6]) cancels under batchnorm's mean subtraction */
    const float* bn1_g   = (const float*)d_in[7];
    const float* bn1_b   = (const float*)d_in[8];
    const float* conv2_w = (const float*)d_in[9];
    const float* conv2_b = (const float*)d_in[10];
    const float* fc1_w   = (const float*)d_in[11];
    const float* fc1_b   = (const float*)d_in[12];
    const float* head_w  = (const float*)d_in[13];
    const float* head_b  = (const float*)d_in[14];
    float* out = (float*)d_out;

    stem_kernel<<<dim3(512, 16), 128>>>(x, stem_w);
    bn0_partial<<<dim3(64, 8), 256>>>();
    bn0_final<<<1, 64>>>(stem_g, stem_b);
    pool0<<<65536, 256>>>();

    double a1 = -5.0*PI_D/180.0, a2 = 5.0*PI_D/180.0;
    gridsample_kernel<<<dim3(128, 16), 128>>>(
        (float)cos(a1), (float)sin(-a1), 0.f,
        (float)sin(a1), (float)cos(a1), 0.f, 0);
    gridsample_kernel<<<dim3(128, 16), 128>>>(
        (float)cos(a2), (float)sin(-a2), 0.f,
        (float)sin(a2), (float)cos(a2), 0.f, 1);

    roialign_kernel<<<176, 256>>>(box);

    conv1_kernel<<<dim3(8, 4, 16), 448>>>(conv1_w);
    conv1_reduce<<<1764, 256>>>();
    bn1_stats<<<64, 256>>>(bn1_g, bn1_b);
    pool1<<<400, 256>>>();
    conv2_kernel<<<128, 256>>>(conv2_w, conv2_b);
    fc1_kernel<<<16, 128>>>(fc1_w, fc1_b);
    head_kernel<<<1, 256>>>(head_w, head_b, out);
}

// round 2
// speedup vs baseline: 1.2343x; 1.2343x over previous
#include <cuda_runtime.h>
#include <math.h>

// ---------------- constants ----------------
#define NB 16
#define C1 64
#define H1 256
#define HP 128
#define CH 704
#define NP 23
#define PI_D 3.14159265358979323846

typedef unsigned long long u64;

// packed fp32x2 helpers (SASS FFMA2 — 2x fp32 FMA per issue, IEEE-exact per lane)
__device__ __forceinline__ u64 ffma2(u64 a, u64 b, u64 c) {
    u64 d;
    asm("fma.rn.f32x2 %0, %1, %2, %3;" : "=l"(d) : "l"(a), "l"(b), "l"(c));
    return d;
}
__device__ __forceinline__ u64 pack2(float x, float y) {
    u64 d;
    asm("mov.b64 %0, {%1, %2};" : "=l"(d) : "f"(x), "f"(y));
    return d;
}
__device__ __forceinline__ void unpack2(u64 v, float& x, float& y) {
    asm("mov.b64 {%0, %1}, %2;" : "=f"(x), "=f"(y) : "l"(v));
}

// ---------------- device scratch ----------------
__device__ float g_conv0[(size_t)NB*C1*H1*H1];       // 256 MB
__device__ float g_f   [(size_t)NB*C1*HP*HP];        // 64 MB
__device__ float g_xt1 [(size_t)NB*C1*HP*HP];
__device__ float g_xt2 [(size_t)NB*C1*HP*HP];
__device__ float g_h   [(size_t)NB*CH*NP*NP];
__device__ float g_c1p [(size_t)8*NB*64*441];
__device__ float g_c1  [(size_t)NB*64*441];
__device__ float g_p1  [(size_t)NB*64*100];
__device__ float g_c2  [(size_t)NB*32*64];
__device__ float g_fc1 [(size_t)NB*128];
__device__ float2 g_bn0part[64*8];
__device__ float g_scale0[64], g_shift0[64];
__device__ float g_scale1[64], g_shift1[64];

// ---------------- stem conv: 7x7 s2 p3, 3->64 ch, FFMA2 ----------------
// block = one output row (256 px); thread = 2 pixels x 64 channels.
// channels packed in pairs; input value duplicated (v,v) once per tap.
__global__ __launch_bounds__(128) void stem_kernel(const float* __restrict__ x,
                                                   const float* __restrict__ w) {
    __shared__ float ws[147*64];   // [idx][co], idx = c*49+kh*7+kw
    int b = blockIdx.y, oh = blockIdx.x;
    int t = threadIdx.x;
    for (int i = t; i < 9408; i += 128) {
        int co = i / 147, idx = i % 147;
        ws[idx*64 + co] = w[i];
    }
    __syncthreads();
    u64 acc0[32], acc1[32];        // acc[k] = channels (2k,2k+1); pixel0 / pixel1
#pragma unroll
    for (int i = 0; i < 32; i++) { acc0[i] = 0ull; acc1[i] = 0ull; }
#pragma unroll 1
    for (int c = 0; c < 3; c++) {
#pragma unroll 1
        for (int kh = 0; kh < 7; kh++) {
            int ih = oh*2 - 3 + kh;
            bool vrow = ((unsigned)ih < 512u);
            const float* xrow = x + (((size_t)b*512 + ih)*512)*3 + c;
#pragma unroll
            for (int kw = 0; kw < 7; kw++) {
                int iw0 = 4*t - 3 + kw;            // pixel0: ow=2t
                float v0 = (vrow && (unsigned)iw0 < 512u) ? xrow[(size_t)iw0*3] : 0.f;
                float v1 = (vrow && (unsigned)(iw0+2) < 512u) ? xrow[(size_t)(iw0+2)*3] : 0.f;
                u64 pv0 = pack2(v0, v0);
                u64 pv1 = pack2(v1, v1);
                int idx = (c*7 + kh)*7 + kw;
                const ulonglong2* wp = (const ulonglong2*)(ws + idx*64);
#pragma unroll
                for (int g = 0; g < 16; g++) {
                    ulonglong2 q = wp[g];          // channels 4g..4g+3 as 2 pairs
                    acc0[2*g  ] = ffma2(pv0, q.x, acc0[2*g  ]);
                    acc0[2*g+1] = ffma2(pv0, q.y, acc0[2*g+1]);
                    acc1[2*g  ] = ffma2(pv1, q.x, acc1[2*g  ]);
                    acc1[2*g+1] = ffma2(pv1, q.y, acc1[2*g+1]);
                }
            }
        }
    }
    // store: per channel, float2 (pix0, pix1) — fully coalesced
    size_t base = ((size_t)b*64)*65536 + (size_t)oh*256 + 2*t;
#pragma unroll
    for (int k = 0; k < 32; k++) {
        float a0, a1, b0, b1;
        unpack2(acc0[k], a0, a1);   // ch 2k, 2k+1 @ pix0
        unpack2(acc1[k], b0, b1);   // ch 2k, 2k+1 @ pix1
        *(float2*)(g_conv0 + base + (size_t)(2*k  )*65536) = make_float2(a0, b0);
        *(float2*)(g_conv0 + base + (size_t)(2*k+1)*65536) = make_float2(a1, b1);
    }
}

// ---------------- bn0 stats (deterministic two-stage) ----------------
__global__ void bn0_partial() {
    int c = blockIdx.x, sl = blockIdx.y;
    float s = 0.f, q = 0.f;
    for (int j = sl*131072 + threadIdx.x; j < (sl+1)*131072; j += 256) {
        int b = j >> 16, pix = j & 65535;
        float v = g_conv0[((size_t)(b*64 + c))*65536 + pix];
        s += v; q += v*v;
    }
    __shared__ float rs[256], rq[256];
    rs[threadIdx.x] = s; rq[threadIdx.x] = q; __syncthreads();
    for (int st = 128; st > 0; st >>= 1) {
        if (threadIdx.x < st) { rs[threadIdx.x] += rs[threadIdx.x+st]; rq[threadIdx.x] += rq[threadIdx.x+st]; }
        __syncthreads();
    }
    if (threadIdx.x == 0) g_bn0part[c*8 + sl] = make_float2(rs[0], rq[0]);
}

__global__ void bn0_final(const float* __restrict__ g, const float* __restrict__ bb) {
    int c = threadIdx.x; if (c >= 64) return;
    float s = 0.f, q = 0.f;
    for (int i = 0; i < 8; i++) { float2 p = g_bn0part[c*8+i]; s += p.x; q += p.y; }
    const float inv = 1.f / 1048576.f;
    float m = s*inv, var = q*inv - m*m;
    float sc = g[c] * rsqrtf(var + 1e-5f);
    g_scale0[c] = sc; g_shift0[c] = bb[c] - m*sc;
}

// ---------------- fused bn+relu+maxpool 3x3 s2 p1 ----------------
__global__ void pool0() {
    int idx = blockIdx.x*256 + threadIdx.x;          // 16*64*128*128 total
    int ow = idx & 127, oh = (idx >> 7) & 127, c = (idx >> 14) & 63, b = idx >> 20;
    float sc = g_scale0[c], sh = g_shift0[c];
    const float* src = g_conv0 + ((size_t)(b*64 + c))*65536;
    float m = 0.f;   // relu >= 0
#pragma unroll
    for (int dy = 0; dy < 3; dy++) {
        int ih = oh*2 - 1 + dy;
        if ((unsigned)ih >= 256u) continue;
#pragma unroll
        for (int dx = 0; dx < 3; dx++) {
            int iw = ow*2 - 1 + dx;
            if ((unsigned)iw >= 256u) continue;
            m = fmaxf(m, fmaxf(sc*src[ih*256 + iw] + sh, 0.f));
        }
    }
    g_f[idx] = m;
}

// ---------------- grid_sample with affine grid ----------------
__global__ void gridsample_kernel(float t00, float t01, float t02,
                                  float t10, float t11, float t12, int which) {
    int w = threadIdx.x, hh = blockIdx.x, b = blockIdx.y;
    float* out = which ? g_xt2 : g_xt1;
    float gx = (float)(2*w + 1) * (1.f/128.f) - 1.f;
    float gy = (float)(2*hh + 1) * (1.f/128.f) - 1.f;
    float grx = gx*t00 + gy*t01 + t02;
    float gry = gx*t10 + gy*t11 + t12;
    float ix = ((grx + 1.f)*128.f - 1.f)*0.5f;
    float iy = ((gry + 1.f)*128.f - 1.f)*0.5f;
    float x0f = floorf(ix), y0f = floorf(iy);
    int x0 = (int)x0f, y0 = (int)y0f;
    float wa = (x0f + 1.f - ix)*(y0f + 1.f - iy);
    float wb = (x0f + 1.f - ix)*(iy - y0f);
    float wc = (ix - x0f)*(y0f + 1.f - iy);
    float wd = (ix - x0f)*(iy - y0f);
    int   off[4]; float wf[4];
    float wt[4] = {wa, wb, wc, wd};
    int xs2[2] = {x0, x0 + 1}, ys2[2] = {y0, y0 + 1};
#pragma unroll
    for (int dx = 0; dx < 2; dx++)
#pragma unroll
        for (int dy = 0; dy < 2; dy++) {
            int xx = xs2[dx], yy = ys2[dy];
            bool valid = ((unsigned)xx < 128u) && ((unsigned)yy < 128u);
            int xc = min(max(xx, 0), 127), yc = min(max(yy, 0), 127);
            int k = dx*2 + dy;
            off[k] = yc*128 + xc;
            wf[k] = valid ? wt[k] : 0.f;
        }
    size_t base = ((size_t)b*64)*16384;
    int pix = hh*128 + w;
    const float* src = g_f + base;
    for (int c = 0; c < 64; c++) {
        const float* sp = src + c*16384;
        out[base + (size_t)c*16384 + pix] =
            sp[off[0]]*wf[0] + sp[off[1]]*wf[1] + sp[off[2]]*wf[2] + sp[off[3]]*wf[3];
    }
}

// ---------------- roialign: writes directly into concat buffer g_h ----------------
__global__ void roialign_kernel(const float* __restrict__ box) {
    int blk = blockIdx.x;            // 16*11
    int b = blk / 11, s = blk % 11;
    const float* feat; int r;
    if (s < 7)       { feat = g_f;   r = s;     }
    else if (s < 9)  { feat = g_xt1; r = s - 7; }
    else             { feat = g_xt2; r = s - 9; }
    const float* bx = box + b*28 + r*4;
    float rx1 = bx[0]*0.25f, ry1 = bx[1]*0.25f, rx2 = bx[2]*0.25f, ry2 = bx[3]*0.25f;
    float bw = fmaxf(rx2 - rx1, 1.f) * (1.f/23.f);
    float bh = fmaxf(ry2 - ry1, 1.f) * (1.f/23.f);
    __shared__ int   sy0[46], sy1[46], sx0[46], sx1[46];
    __shared__ float sly[46], slx[46];
    __shared__ int   sey[46], sex[46];
    int t = threadIdx.x;
    if (t < 46) {
        float pos = (float)(t >> 1) + 0.25f + 0.5f*(float)(t & 1);
        float yv = ry1 + pos*bh;
        sey[t] = (yv < -1.f) || (yv > 128.f);
        float y = fminf(fmaxf(yv, 0.f), 127.f);
        float y0f = floorf(y); int y0 = (int)y0f;
        sy0[t] = y0; sy1[t] = min(y0 + 1, 127); sly[t] = y - y0f;
        float xv = rx1 + pos*bw;
        sex[t] = (xv < -1.f) || (xv > 128.f);
        float xx = fminf(fmaxf(xv, 0.f), 127.f);
        float x0f = floorf(xx); int x0 = (int)x0f;
        sx0[t] = x0; sx1[t] = min(x0 + 1, 127); slx[t] = xx - x0f;
    }
    __syncthreads();
    const float* fb = feat + ((size_t)b*64)*16384;
    float* ob = g_h + ((size_t)(b*704 + s*64))*529;
    for (int o = t; o < 64*529; o += 256) {
        int c = o / 529, pp = o % 529;
        int py = pp / 23, px = pp % 23;
        const float* img = fb + (size_t)c*16384;
        float acc = 0.f;
#pragma unroll
        for (int dy = 0; dy < 2; dy++) {
            int jy = py*2 + dy;
            int yy0 = sy0[jy], yy1 = sy1[jy];
            float ly = sly[jy], hy = 1.f - ly;
            int ey = sey[jy];
#pragma unroll
            for (int dx = 0; dx < 2; dx++) {
                int jx = px*2 + dx;
                int xx0 = sx0[jx], xx1 = sx1[jx];
                float lx = slx[jx], hx = 1.f - lx;
                float v = img[yy0*128 + xx0]*(hy*hx) + img[yy0*128 + xx1]*(hy*lx)
                        + img[yy1*128 + xx0]*(ly*hx) + img[yy1*128 + xx1]*(ly*lx);
                if (ey || sex[jx]) v = 0.f;
                acc += v;
            }
        }
        ob[o] = acc * 0.25f;
    }
}

// ---------------- conv1 3x3 valid, 704->64, FFMA2, ci-split partials ----------------
__global__ __launch_bounds__(448) void conv1_kernel(const float* __restrict__ w) {
    int split = blockIdx.x;   // 0..7 (88 ci each)
    int cog   = blockIdx.y;   // 0..1 (32 couts each)
    int b     = blockIdx.z;
    __shared__ float tile[529];
    __shared__ float ws[288];            // [k][j], j = co_local 0..31
    int t = threadIdx.x;
    int oh = t / 21, ow = t % 21;
    bool active = (t < 441);
    u64 acc[16];                          // channel pairs (2k, 2k+1)
#pragma unroll
    for (int i = 0; i < 16; i++) acc[i] = 0ull;
    int ci0 = split*88;
    for (int ci = ci0; ci < ci0 + 88; ci++) {
        __syncthreads();
        for (int i = t; i < 529; i += 448)
            tile[i] = g_h[((size_t)(b*704 + ci))*529 + i];
        if (t < 288) {
            int j = t / 9, k = t % 9;
            ws[k*32 + j] = w[((size_t)(cog*32 + j)*704 + ci)*9 + k];
        }
        __syncthreads();
        if (active) {
            float r[9];
#pragma unroll
            for (int kh = 0; kh < 3; kh++)
#pragma unroll
                for (int kw = 0; kw < 3; kw++)
                    r[kh*3 + kw] = tile[(oh + kh)*23 + ow + kw];
#pragma unroll
            for (int k = 0; k < 9; k++) {
                u64 pv = pack2(r[k], r[k]);
                const ulonglong2* w2 = (const ulonglong2*)(ws + k*32);
#pragma unroll
                for (int g = 0; g < 8; g++) {
                    ulonglong2 q = w2[g];
                    acc[2*g  ] = ffma2(pv, q.x, acc[2*g  ]);
                    acc[2*g+1] = ffma2(pv, q.y, acc[2*g+1]);
                }
            }
        }
    }
    if (active) {
#pragma unroll
        for (int k = 0; k < 16; k++) {
            float lo, hi;
            unpack2(acc[k], lo, hi);
            int co = cog*32 + 2*k;
            g_c1p[(((size_t)split*16 + b)*64 + co    )*441 + t] = lo;
            g_c1p[(((size_t)split*16 + b)*64 + co + 1)*441 + t] = hi;
        }
    }
}

__global__ void conv1_reduce() {
    int o = blockIdx.x*256 + threadIdx.x;
    if (o >= 16*64*441) return;
    float s = 0.f;
#pragma unroll
    for (int k = 0; k < 8; k++) s += g_c1p[(size_t)k*16*64*441 + o];
    g_c1[o] = s;
}

// ---------------- bn1 stats ----------------
__global__ void bn1_stats(const float* __restrict__ g, const float* __restrict__ bb) {
    int c = blockIdx.x;
    float s = 0.f, q = 0.f;
    for (int i = threadIdx.x; i < 16*441; i += 256) {
        int b = i / 441, t = i % 441;
        float v = g_c1[((size_t)(b*64 + c))*441 + t];
        s += v; q += v*v;
    }
    __shared__ float rs[256], rq[256];
    rs[threadIdx.x] = s; rq[threadIdx.x] = q; __syncthreads();
    for (int st = 128; st > 0; st >>= 1) {
        if (threadIdx.x < st) { rs[threadIdx.x] += rs[threadIdx.x+st]; rq[threadIdx.x] += rq[threadIdx.x+st]; }
        __syncthreads();
    }
    if (threadIdx.x == 0) {
        const float inv = 1.f / 7056.f;
        float m = rs[0]*inv, var = rq[0]*inv - m*m;
        float sc = g[c] * rsqrtf(var + 1e-5f);
        g_scale1[c] = sc; g_shift1[c] = bb[c] - m*sc;
    }
}

// ---------------- bn1+relu+maxpool2x2 ----------------
__global__ void pool1() {
    int idx = blockIdx.x*256 + threadIdx.x;   // 16*64*100
    if (idx >= 102400) return;
    int ow = idx % 10, oh = (idx/10) % 10, c = (idx/100) % 64, b = idx/6400;
    float sc = g_scale1[c], sh = g_shift1[c];
    const float* src = g_c1 + ((size_t)(b*64 + c))*441;
    float m = 0.f;
#pragma unroll
    for (int dy = 0; dy < 2; dy++)
#pragma unroll
        for (int dx = 0; dx < 2; dx++)
            m = fmaxf(m, fmaxf(sc*src[(oh*2 + dy)*21 + ow*2 + dx] + sh, 0.f));
    g_p1[idx] = m;
}

// ---------------- conv2 3x3 valid, 64->32, +bias, relu ----------------
__global__ void conv2_kernel(const float* __restrict__ w, const float* __restrict__ bias) {
    int idx = blockIdx.x*256 + threadIdx.x;   // 16*32*64
    int ow = idx & 7, oh = (idx >> 3) & 7, co = (idx >> 6) & 31, b = idx >> 11;
    const float* src = g_p1 + (size_t)b*6400;
    const float* wp  = w + (size_t)co*576;
    float acc = bias[co];
    for (int ci = 0; ci < 64; ci++) {
        const float* sp = src + ci*100;
        const float* wc = wp + ci*9;
#pragma unroll
        for (int kh = 0; kh < 3; kh++)
#pragma unroll
            for (int kw = 0; kw < 3; kw++)
                acc += sp[(oh + kh)*10 + ow + kw] * wc[kh*3 + kw];
    }
    g_c2[idx] = fmaxf(acc, 0.f);
}

// ---------------- fc1 + relu ----------------
__global__ __launch_bounds__(128) void fc1_kernel(const float* __restrict__ w, const float* __restrict__ bias) {
    int b = blockIdx.x, j = threadIdx.x;
    __shared__ float xv[2048];
    for (int i = j; i < 2048; i += 128) xv[i] = g_c2[(size_t)b*2048 + i];
    __syncthreads();
    const float4* wp = (const float4*)(w + (size_t)j*2048);
    const float4* xp = (const float4*)xv;
    float acc = 0.f;
#pragma unroll 4
    for (int k = 0; k < 512; k++) {
        float4 wv = wp[k], x4 = xp[k];
        acc += wv.x*x4.x + wv.y*x4.y + wv.z*x4.z + wv.w*x4.w;
    }
    g_fc1[b*128 + j] = fmaxf(acc + bias[j], 0.f);
}

// ---------------- head + tanh ----------------
__global__ void head_kernel(const float* __restrict__ w, const float* __restrict__ bias,
                            float* __restrict__ out) {
    int t = threadIdx.x; if (t >= 192) return;
    int b = t / 12, j = t % 12;
    const float* wp = w + j*128;
    const float* xp = g_fc1 + b*128;
    float acc = bias[j];
#pragma unroll 4
    for (int k = 0; k < 128; k++) acc += wp[k]*xp[k];
    out[b*12 + j] = tanhf(acc);
}

// ---------------- launch ----------------
extern "C" void kernel_launch(void* const* d_in, const int* in_sizes, int n_in,
                              void* d_out, int out_size) {
    const float* x       = (const float*)d_in[0];
    const float* box     = (const float*)d_in[1];
    const float* stem_w  = (const float*)d_in[2];
    const float* stem_g  = (const float*)d_in[3];
    const float* stem_b  = (const float*)d_in[4];
    const float* conv1_w = (const float*)d_in[5];
    /* conv1_b (d_in[6]) cancels under batchnorm's mean subtraction */
    const float* bn1_g   = (const float*)d_in[7];
    const float* bn1_b   = (const float*)d_in[8];
    const float* conv2_w = (const float*)d_in[9];
    const float* conv2_b = (const float*)d_in[10];
    const float* fc1_w   = (const float*)d_in[11];
    const float* fc1_b   = (const float*)d_in[12];
    const float* head_w  = (const float*)d_in[13];
    const float* head_b  = (const float*)d_in[14];
    float* out = (float*)d_out;

    stem_kernel<<<dim3(256, 16), 128>>>(x, stem_w);
    bn0_partial<<<dim3(64, 8), 256>>>();
    bn0_final<<<1, 64>>>(stem_g, stem_b);
    pool0<<<65536, 256>>>();

    double a1 = -5.0*PI_D/180.0, a2 = 5.0*PI_D/180.0;
    gridsample_kernel<<<dim3(128, 16), 128>>>(
        (float)cos(a1), (float)sin(-a1), 0.f,
        (float)sin(a1), (float)cos(a1), 0.f, 0);
    gridsample_kernel<<<dim3(128, 16), 128>>>(
        (float)cos(a2), (float)sin(-a2), 0.f,
        (float)sin(a2), (float)cos(a2), 0.f, 1);

    roialign_kernel<<<176, 256>>>(box);

    conv1_kernel<<<dim3(8, 2, 16), 448>>>(conv1_w);
    conv1_reduce<<<1764, 256>>>();
    bn1_stats<<<64, 256>>>(bn1_g, bn1_b);
    pool1<<<400, 256>>>();
    conv2_kernel<<<128, 256>>>(conv2_w, conv2_b);
    fc1_kernel<<<16, 128>>>(fc1_w, fc1_b);
    head_kernel<<<1, 256>>>(head_w, head_b, out);
}

// round 3
// speedup vs baseline: 1.2830x; 1.0394x over previous
#include <cuda_runtime.h>
#include <math.h>

// ---------------- constants ----------------
#define NB 16
#define C1 64
#define H1 256
#define HP 128
#define CH 704
#define NP 23
#define PI_D 3.14159265358979323846

typedef unsigned long long u64;

// packed fp32x2 helpers (SASS FFMA2 — 2x fp32 FMA per issue, IEEE-exact per lane)
__device__ __forceinline__ u64 ffma2(u64 a, u64 b, u64 c) {
    u64 d;
    asm("fma.rn.f32x2 %0, %1, %2, %3;" : "=l"(d) : "l"(a), "l"(b), "l"(c));
    return d;
}
__device__ __forceinline__ u64 pack2(float x, float y) {
    u64 d;
    asm("mov.b64 %0, {%1, %2};" : "=l"(d) : "f"(x), "f"(y));
    return d;
}
__device__ __forceinline__ void unpack2(u64 v, float& x, float& y) {
    asm("mov.b64 {%0, %1}, %2;" : "=f"(x), "=f"(y) : "l"(v));
}

// ---------------- device scratch ----------------
__device__ float g_conv0[(size_t)NB*C1*H1*H1];       // 256 MB
__device__ float g_f   [(size_t)NB*C1*HP*HP];        // 64 MB
__device__ float g_xt1 [(size_t)NB*C1*HP*HP];
__device__ float g_xt2 [(size_t)NB*C1*HP*HP];
__device__ float g_h   [(size_t)NB*CH*NP*NP];
__device__ float g_c1p [(size_t)8*NB*64*441];
__device__ float g_c1  [(size_t)NB*64*441];
__device__ float g_p1  [(size_t)NB*64*100];
__device__ float g_c2  [(size_t)NB*32*64];
__device__ float g_fc1 [(size_t)NB*128];
__device__ float g_bn0row[2*64*4096];                // [sum/sq][ch][block]
__device__ float g_scale0[64], g_shift0[64];
__device__ float g_scale1[64], g_shift1[64];

// ---------------- stem conv: 7x7 s2 p3, 3->64 ch, FFMA2 ----------------
// block = one output row (256 px), 256 threads.
// thread: half = t>>7 selects channels [32h,32h+32); tt = t&127 -> pixels (2tt, 2tt+1).
// Also emits per-block bn partial sums/sumsq (deterministic tree).
__global__ __launch_bounds__(256, 2) void stem_kernel(const float* __restrict__ x,
                                                      const float* __restrict__ w) {
    __shared__ float smem_buf[9408];     // weights [idx][64]; later reused as red[64][129]
    float* ws = smem_buf;
    int b = blockIdx.y, oh = blockIdx.x;
    int t = threadIdx.x;
    for (int i = t; i < 9408; i += 256) {
        int co = i / 147, idx = i % 147;
        ws[idx*64 + co] = w[i];
    }
    __syncthreads();
    int half = t >> 7, tt = t & 127;
    u64 acc0[16], acc1[16];              // acc[k] = local channel pair (2k,2k+1); pix0 / pix1
#pragma unroll
    for (int i = 0; i < 16; i++) { acc0[i] = 0ull; acc1[i] = 0ull; }
#pragma unroll 1
    for (int c = 0; c < 3; c++) {
#pragma unroll 1
        for (int kh = 0; kh < 7; kh++) {
            int ih = oh*2 - 3 + kh;
            bool vrow = ((unsigned)ih < 512u);
            const float* xrow = x + (((size_t)b*512 + ih)*512)*3 + c;
#pragma unroll
            for (int kw = 0; kw < 7; kw++) {
                int iw0 = 4*tt - 3 + kw;
                float v0 = (vrow && (unsigned)iw0 < 512u) ? xrow[(size_t)iw0*3] : 0.f;
                float v1 = (vrow && (unsigned)(iw0+2) < 512u) ? xrow[(size_t)(iw0+2)*3] : 0.f;
                u64 pv0 = pack2(v0, v0);
                u64 pv1 = pack2(v1, v1);
                int idx = (c*7 + kh)*7 + kw;
                const ulonglong2* wp = (const ulonglong2*)(ws + idx*64 + half*32);
#pragma unroll
                for (int g = 0; g < 8; g++) {
                    ulonglong2 q = wp[g];
                    acc0[2*g  ] = ffma2(pv0, q.x, acc0[2*g  ]);
                    acc0[2*g+1] = ffma2(pv0, q.y, acc0[2*g+1]);
                    acc1[2*g  ] = ffma2(pv1, q.x, acc1[2*g  ]);
                    acc1[2*g+1] = ffma2(pv1, q.y, acc1[2*g+1]);
                }
            }
        }
    }
    // store conv output: per channel float2 (pix0, pix1) — coalesced
    size_t base = ((size_t)(b*64 + half*32))*65536 + (size_t)oh*256 + 2*tt;
#pragma unroll
    for (int k = 0; k < 16; k++) {
        float l0, h0, l1, h1;
        unpack2(acc0[k], l0, h0);
        unpack2(acc1[k], l1, h1);
        *(float2*)(g_conv0 + base + (size_t)(2*k  )*65536) = make_float2(l0, l1);
        *(float2*)(g_conv0 + base + (size_t)(2*k+1)*65536) = make_float2(h0, h1);
    }
    // ---- bn partial stats over this row (deterministic) ----
    int blk = b*256 + oh;
    float* red = smem_buf;               // [64][129]
    int rc = t >> 2, rq = t & 3;
    // pass 1: sums
    __syncthreads();
#pragma unroll
    for (int k = 0; k < 16; k++) {
        float l0, h0, l1, h1;
        unpack2(acc0[k], l0, h0);
        unpack2(acc1[k], l1, h1);
        red[(half*32 + 2*k  )*129 + tt] = l0 + l1;
        red[(half*32 + 2*k+1)*129 + tt] = h0 + h1;
    }
    __syncthreads();
    {
        float s = 0.f;
#pragma unroll
        for (int i = 0; i < 32; i++) s += red[rc*129 + rq*32 + i];
        s += __shfl_xor_sync(0xffffffffu, s, 1);
        s += __shfl_xor_sync(0xffffffffu, s, 2);
        if (rq == 0) g_bn0row[rc*4096 + blk] = s;
    }
    __syncthreads();
    // pass 2: sums of squares
#pragma unroll
    for (int k = 0; k < 16; k++) {
        float l0, h0, l1, h1;
        unpack2(acc0[k], l0, h0);
        unpack2(acc1[k], l1, h1);
        red[(half*32 + 2*k  )*129 + tt] = l0*l0 + l1*l1;
        red[(half*32 + 2*k+1)*129 + tt] = h0*h0 + h1*h1;
    }
    __syncthreads();
    {
        float s = 0.f;
#pragma unroll
        for (int i = 0; i < 32; i++) s += red[rc*129 + rq*32 + i];
        s += __shfl_xor_sync(0xffffffffu, s, 1);
        s += __shfl_xor_sync(0xffffffffu, s, 2);
        if (rq == 0) g_bn0row[(64 + rc)*4096 + blk] = s;
    }
}

// ---------------- bn0 final: reduce 4096 row-partials per channel ----------------
__global__ void bn0_final(const float* __restrict__ g, const float* __restrict__ bb) {
    int c = blockIdx.x;
    float s = 0.f, q = 0.f;
    for (int i = threadIdx.x; i < 4096; i += 256) {
        s += g_bn0row[c*4096 + i];
        q += g_bn0row[(64 + c)*4096 + i];
    }
    __shared__ float rs[256], rq[256];
    rs[threadIdx.x] = s; rq[threadIdx.x] = q; __syncthreads();
    for (int st = 128; st > 0; st >>= 1) {
        if (threadIdx.x < st) { rs[threadIdx.x] += rs[threadIdx.x+st]; rq[threadIdx.x] += rq[threadIdx.x+st]; }
        __syncthreads();
    }
    if (threadIdx.x == 0) {
        const float inv = 1.f / 1048576.f;
        float m = rs[0]*inv, var = rq[0]*inv - m*m;
        float sc = g[c] * rsqrtf(var + 1e-5f);
        g_scale0[c] = sc; g_shift0[c] = bb[c] - m*sc;
    }
}

// ---------------- fused bn+relu+maxpool 3x3 s2 p1, 2 outputs/thread ----------------
__global__ void pool0() {
    int idx = blockIdx.x*256 + threadIdx.x;          // 16*64*128*64
    int owp = idx & 63, oh = (idx >> 6) & 127, c = (idx >> 13) & 63, b = idx >> 19;
    float sc = g_scale0[c], sh = g_shift0[c];
    const float* src = g_conv0 + ((size_t)(b*64 + c))*65536;
    // raw max & min over each window (affine is monotone; relu after)
    float mx0 = -3.4e38f, mn0 = 3.4e38f, mx1 = -3.4e38f, mn1 = 3.4e38f;
    int c0 = 4*owp;
#pragma unroll
    for (int dy = 0; dy < 3; dy++) {
        int ih = oh*2 - 1 + dy;
        if ((unsigned)ih >= 256u) continue;
        const float* r = src + ih*256;
        float4 qv = *(const float4*)(r + c0);
        if (owp > 0) {
            float left = r[c0 - 1];
            mx0 = fmaxf(mx0, left); mn0 = fminf(mn0, left);
        }
        mx0 = fmaxf(mx0, fmaxf(qv.x, qv.y));
        mn0 = fminf(mn0, fminf(qv.x, qv.y));
        mx1 = fmaxf(mx1, fmaxf(qv.y, fmaxf(qv.z, qv.w)));
        mn1 = fminf(mn1, fminf(qv.y, fminf(qv.z, qv.w)));
    }
    float v0 = (sc >= 0.f) ? sc*mx0 + sh : sc*mn0 + sh;
    float v1 = (sc >= 0.f) ? sc*mx1 + sh : sc*mn1 + sh;
    size_t obase = ((size_t)(b*64 + c))*16384 + (size_t)oh*128 + 2*owp;
    *(float2*)(g_f + obase) = make_float2(fmaxf(v0, 0.f), fmaxf(v1, 0.f));
}

// ---------------- grid_sample, both thetas in one launch ----------------
__global__ void gridsample_kernel(float p00, float p01, float p02,
                                  float p10, float p11, float p12,
                                  float q00, float q01, float q02,
                                  float q10, float q11, float q12) {
    int w = threadIdx.x, hh = blockIdx.x, b = blockIdx.y, which = blockIdx.z;
    float t00 = which ? q00 : p00, t01 = which ? q01 : p01, t02 = which ? q02 : p02;
    float t10 = which ? q10 : p10, t11 = which ? q11 : p11, t12 = which ? q12 : p12;
    float* out = which ? g_xt2 : g_xt1;
    float gx = (float)(2*w + 1) * (1.f/128.f) - 1.f;
    float gy = (float)(2*hh + 1) * (1.f/128.f) - 1.f;
    float grx = gx*t00 + gy*t01 + t02;
    float gry = gx*t10 + gy*t11 + t12;
    float ix = ((grx + 1.f)*128.f - 1.f)*0.5f;
    float iy = ((gry + 1.f)*128.f - 1.f)*0.5f;
    float x0f = floorf(ix), y0f = floorf(iy);
    int x0 = (int)x0f, y0 = (int)y0f;
    float wa = (x0f + 1.f - ix)*(y0f + 1.f - iy);
    float wb = (x0f + 1.f - ix)*(iy - y0f);
    float wc = (ix - x0f)*(y0f + 1.f - iy);
    float wd = (ix - x0f)*(iy - y0f);
    int   off[4]; float wf[4];
    float wt[4] = {wa, wb, wc, wd};
    int xs2[2] = {x0, x0 + 1}, ys2[2] = {y0, y0 + 1};
#pragma unroll
    for (int dx = 0; dx < 2; dx++)
#pragma unroll
        for (int dy = 0; dy < 2; dy++) {
            int xx = xs2[dx], yy = ys2[dy];
            bool valid = ((unsigned)xx < 128u) && ((unsigned)yy < 128u);
            int xc = min(max(xx, 0), 127), yc = min(max(yy, 0), 127);
            int k = dx*2 + dy;
            off[k] = yc*128 + xc;
            wf[k] = valid ? wt[k] : 0.f;
        }
    size_t base = ((size_t)b*64)*16384;
    int pix = hh*128 + w;
    const float* src = g_f + base;
    for (int c = 0; c < 64; c++) {
        const float* sp = src + c*16384;
        out[base + (size_t)c*16384 + pix] =
            sp[off[0]]*wf[0] + sp[off[1]]*wf[1] + sp[off[2]]*wf[2] + sp[off[3]]*wf[3];
    }
}

// ---------------- roialign: 4-way channel split, writes into concat g_h ----------------
__global__ void roialign_kernel(const float* __restrict__ box) {
    int blk = blockIdx.x;            // 16*11
    int cq  = blockIdx.y;            // 0..3 -> channels [16cq, 16cq+16)
    int b = blk / 11, s = blk % 11;
    const float* feat; int r;
    if (s < 7)       { feat = g_f;   r = s;     }
    else if (s < 9)  { feat = g_xt1; r = s - 7; }
    else             { feat = g_xt2; r = s - 9; }
    const float* bx = box + b*28 + r*4;
    float rx1 = bx[0]*0.25f, ry1 = bx[1]*0.25f, rx2 = bx[2]*0.25f, ry2 = bx[3]*0.25f;
    float bw = fmaxf(rx2 - rx1, 1.f) * (1.f/23.f);
    float bh = fmaxf(ry2 - ry1, 1.f) * (1.f/23.f);
    __shared__ int   sy0[46], sy1[46], sx0[46], sx1[46];
    __shared__ float sly[46], slx[46];
    __shared__ int   sey[46], sex[46];
    int t = threadIdx.x;
    if (t < 46) {
        float pos = (float)(t >> 1) + 0.25f + 0.5f*(float)(t & 1);
        float yv = ry1 + pos*bh;
        sey[t] = (yv < -1.f) || (yv > 128.f);
        float y = fminf(fmaxf(yv, 0.f), 127.f);
        float y0f = floorf(y); int y0 = (int)y0f;
        sy0[t] = y0; sy1[t] = min(y0 + 1, 127); sly[t] = y - y0f;
        float xv = rx1 + pos*bw;
        sex[t] = (xv < -1.f) || (xv > 128.f);
        float xx = fminf(fmaxf(xv, 0.f), 127.f);
        float x0f = floorf(xx); int x0 = (int)x0f;
        sx0[t] = x0; sx1[t] = min(x0 + 1, 127); slx[t] = xx - x0f;
    }
    __syncthreads();
    const float* fb = feat + ((size_t)b*64)*16384;
    float* ob = g_h + ((size_t)(b*704 + s*64))*529;
    for (int o = t; o < 16*529; o += 256) {
        int c = cq*16 + o / 529, pp = o % 529;
        int py = pp / 23, px = pp % 23;
        const float* img = fb + (size_t)c*16384;
        float acc = 0.f;
#pragma unroll
        for (int dy = 0; dy < 2; dy++) {
            int jy = py*2 + dy;
            int yy0 = sy0[jy], yy1 = sy1[jy];
            float ly = sly[jy], hy = 1.f - ly;
            int ey = sey[jy];
#pragma unroll
            for (int dx = 0; dx < 2; dx++) {
                int jx = px*2 + dx;
                int xx0 = sx0[jx], xx1 = sx1[jx];
                float lx = slx[jx], hx = 1.f - lx;
                float v = img[yy0*128 + xx0]*(hy*hx) + img[yy0*128 + xx1]*(hy*lx)
                        + img[yy1*128 + xx0]*(ly*hx) + img[yy1*128 + xx1]*(ly*lx);
                if (ey || sex[jx]) v = 0.f;
                acc += v;
            }
        }
        ob[(size_t)c*529 + pp] = acc * 0.25f;
    }
}

// ---------------- conv1 3x3 valid, 704->64, FFMA2, ci-split partials ----------------
__global__ __launch_bounds__(448) void conv1_kernel(const float* __restrict__ w) {
    int split = blockIdx.x;   // 0..7 (88 ci each)
    int cog   = blockIdx.y;   // 0..1 (32 couts each)
    int b     = blockIdx.z;
    __shared__ float tile[529];
    __shared__ float ws[288];            // [k][j], j = co_local 0..31
    int t = threadIdx.x;
    int oh = t / 21, ow = t % 21;
    bool active = (t < 441);
    u64 acc[16];
#pragma unroll
    for (int i = 0; i < 16; i++) acc[i] = 0ull;
    int ci0 = split*88;
    for (int ci = ci0; ci < ci0 + 88; ci++) {
        __syncthreads();
        for (int i = t; i < 529; i += 448)
            tile[i] = g_h[((size_t)(b*704 + ci))*529 + i];
        if (t < 288) {
            int j = t / 9, k = t % 9;
            ws[k*32 + j] = w[((size_t)(cog*32 + j)*704 + ci)*9 + k];
        }
        __syncthreads();
        if (active) {
            float r[9];
#pragma unroll
            for (int kh = 0; kh < 3; kh++)
#pragma unroll
                for (int kw = 0; kw < 3; kw++)
                    r[kh*3 + kw] = tile[(oh + kh)*23 + ow + kw];
#pragma unroll
            for (int k = 0; k < 9; k++) {
                u64 pv = pack2(r[k], r[k]);
                const ulonglong2* w2 = (const ulonglong2*)(ws + k*32);
#pragma unroll
                for (int g = 0; g < 8; g++) {
                    ulonglong2 q = w2[g];
                    acc[2*g  ] = ffma2(pv, q.x, acc[2*g  ]);
                    acc[2*g+1] = ffma2(pv, q.y, acc[2*g+1]);
                }
            }
        }
    }
    if (active) {
#pragma unroll
        for (int k = 0; k < 16; k++) {
            float lo, hi;
            unpack2(acc[k], lo, hi);
            int co = cog*32 + 2*k;
            g_c1p[(((size_t)split*16 + b)*64 + co    )*441 + t] = lo;
            g_c1p[(((size_t)split*16 + b)*64 + co + 1)*441 + t] = hi;
        }
    }
}

__global__ void conv1_reduce() {
    int o = blockIdx.x*256 + threadIdx.x;
    if (o >= 16*64*441) return;
    float s = 0.f;
#pragma unroll
    for (int k = 0; k < 8; k++) s += g_c1p[(size_t)k*16*64*441 + o];
    g_c1[o] = s;
}

// ---------------- bn1 stats ----------------
__global__ void bn1_stats(const float* __restrict__ g, const float* __restrict__ bb) {
    int c = blockIdx.x;
    float s = 0.f, q = 0.f;
    for (int i = threadIdx.x; i < 16*441; i += 256) {
        int b = i / 441, t = i % 441;
        float v = g_c1[((size_t)(b*64 + c))*441 + t];
        s += v; q += v*v;
    }
    __shared__ float rs[256], rq[256];
    rs[threadIdx.x] = s; rq[threadIdx.x] = q; __syncthreads();
    for (int st = 128; st > 0; st >>= 1) {
        if (threadIdx.x < st) { rs[threadIdx.x] += rs[threadIdx.x+st]; rq[threadIdx.x] += rq[threadIdx.x+st]; }
        __syncthreads();
    }
    if (threadIdx.x == 0) {
        const float inv = 1.f / 7056.f;
        float m = rs[0]*inv, var = rq[0]*inv - m*m;
        float sc = g[c] * rsqrtf(var + 1e-5f);
        g_scale1[c] = sc; g_shift1[c] = bb[c] - m*sc;
    }
}

// ---------------- bn1+relu+maxpool2x2 ----------------
__global__ void pool1() {
    int idx = blockIdx.x*256 + threadIdx.x;   // 16*64*100
    if (idx >= 102400) return;
    int ow = idx % 10, oh = (idx/10) % 10, c = (idx/100) % 64, b = idx/6400;
    float sc = g_scale1[c], sh = g_shift1[c];
    const float* src = g_c1 + ((size_t)(b*64 + c))*441;
    float m = 0.f;
#pragma unroll
    for (int dy = 0; dy < 2; dy++)
#pragma unroll
        for (int dx = 0; dx < 2; dx++)
            m = fmaxf(m, fmaxf(sc*src[(oh*2 + dy)*21 + ow*2 + dx] + sh, 0.f));
    g_p1[idx] = m;
}

// ---------------- conv2 3x3 valid, 64->32, +bias, relu ----------------
__global__ void conv2_kernel(const float* __restrict__ w, const float* __restrict__ bias) {
    int idx = blockIdx.x*256 + threadIdx.x;   // 16*32*64
    int ow = idx & 7, oh = (idx >> 3) & 7, co = (idx >> 6) & 31, b = idx >> 11;
    const float* src = g_p1 + (size_t)b*6400;
    const float* wp  = w + (size_t)co*576;
    float acc = bias[co];
    for (int ci = 0; ci < 64; ci++) {
        const float* sp = src + ci*100;
        const float* wc = wp + ci*9;
#pragma unroll
        for (int kh = 0; kh < 3; kh++)
#pragma unroll
            for (int kw = 0; kw < 3; kw++)
                acc += sp[(oh + kh)*10 + ow + kw] * wc[kh*3 + kw];
    }
    g_c2[idx] = fmaxf(acc, 0.f);
}

// ---------------- fc1 + relu ----------------
__global__ __launch_bounds__(128) void fc1_kernel(const float* __restrict__ w, const float* __restrict__ bias) {
    int b = blockIdx.x, j = threadIdx.x;
    __shared__ float xv[2048];
    for (int i = j; i < 2048; i += 128) xv[i] = g_c2[(size_t)b*2048 + i];
    __syncthreads();
    const float4* wp = (const float4*)(w + (size_t)j*2048);
    const float4* xp = (const float4*)xv;
    float acc = 0.f;
#pragma unroll 4
    for (int k = 0; k < 512; k++) {
        float4 wv = wp[k], x4 = xp[k];
        acc += wv.x*x4.x + wv.y*x4.y + wv.z*x4.z + wv.w*x4.w;
    }
    g_fc1[b*128 + j] = fmaxf(acc + bias[j], 0.f);
}

// ---------------- head + tanh ----------------
__global__ void head_kernel(const float* __restrict__ w, const float* __restrict__ bias,
                            float* __restrict__ out) {
    int t = threadIdx.x; if (t >= 192) return;
    int b = t / 12, j = t % 12;
    const float* wp = w + j*128;
    const float* xp = g_fc1 + b*128;
    float acc = bias[j];
#pragma unroll 4
    for (int k = 0; k < 128; k++) acc += wp[k]*xp[k];
    out[b*12 + j] = tanhf(acc);
}

// ---------------- launch ----------------
extern "C" void kernel_launch(void* const* d_in, const int* in_sizes, int n_in,
                              void* d_out, int out_size) {
    const float* x       = (const float*)d_in[0];
    const float* box     = (const float*)d_in[1];
    const float* stem_w  = (const float*)d_in[2];
    const float* stem_g  = (const float*)d_in[3];
    const float* stem_b  = (const float*)d_in[4];
    const float* conv1_w = (const float*)d_in[5];
    /* conv1_b (d_in[6]) cancels under batchnorm's mean subtraction */
    const float* bn1_g   = (const float*)d_in[7];
    const float* bn1_b   = (const float*)d_in[8];
    const float* conv2_w = (const float*)d_in[9];
    const float* conv2_b = (const float*)d_in[10];
    const float* fc1_w   = (const float*)d_in[11];
    const float* fc1_b   = (const float*)d_in[12];
    const float* head_w  = (const float*)d_in[13];
    const float* head_b  = (const float*)d_in[14];
    float* out = (float*)d_out;

    stem_kernel<<<dim3(256, 16), 256>>>(x, stem_w);
    bn0_final<<<64, 256>>>(stem_g, stem_b);
    pool0<<<32768, 256>>>();

    double a1 = -5.0*PI_D/180.0, a2 = 5.0*PI_D/180.0;
    gridsample_kernel<<<dim3(128, 16, 2), 128>>>(
        (float)cos(a1), (float)sin(-a1), 0.f, (float)sin(a1), (float)cos(a1), 0.f,
        (float)cos(a2), (float)sin(-a2), 0.f, (float)sin(a2), (float)cos(a2), 0.f);

    roialign_kernel<<<dim3(176, 4), 256>>>(box);

    conv1_kernel<<<dim3(8, 2, 16), 448>>>(conv1_w);
    conv1_reduce<<<1764, 256>>>();
    bn1_stats<<<64, 256>>>(bn1_g, bn1_b);
    pool1<<<400, 256>>>();
    conv2_kernel<<<128, 256>>>(conv2_w, conv2_b);
    fc1_kernel<<<16, 128>>>(fc1_w, fc1_b);
    head_kernel<<<1, 256>>>(head_w, head_b, out);
}